// round 1
// baseline (speedup 1.0000x reference)
#include <cuda_runtime.h>
#include <cuda_bf16.h>
#include <math.h>

#define BATCH 4
#define SEQ 2048
#define EMB 1024
#define HEADS 16
#define HD 64
#define TOKENS (BATCH * SEQ)          // 8192
#define QKV_COLS (3 * EMB)            // 3072

// Scratch (static device globals — allocation-free per harness rules)
__device__ float g_qkv[TOKENS * QKV_COLS];     // [token, 3072]; per head h: q@h*192, k@h*192+64, v@h*192+128
__device__ float g_attn[TOKENS * EMB];         // [token, H*D]

// ---------------------------------------------------------------------------
// FP32 SGEMM with bias: C[M,N] = A[M,K] @ B[K,N] + bias[N]
// BM=BN=128, BK=8, TM=TN=8, 256 threads. Requires M%128==0, N%128==0, K%8==0.
// ---------------------------------------------------------------------------
__global__ __launch_bounds__(256)
void sgemm_bias(const float* __restrict__ A, const float* __restrict__ B,
                const float* __restrict__ bias, float* __restrict__ C,
                int M, int N, int K)
{
    const int BM = 128, BN = 128, BK = 8, TM = 8, TN = 8;
    __shared__ float As[BK][BM];
    __shared__ float Bs[BK][BN];

    const int tid  = threadIdx.x;
    const int tRow = tid / 16;          // 0..15
    const int tCol = tid % 16;          // 0..15

    const float* Ablk = A + (size_t)blockIdx.y * BM * K;
    const float* Bblk = B + (size_t)blockIdx.x * BN;

    const int aRow  = tid / 2;          // 0..127
    const int aCol  = (tid % 2) * 4;    // 0 or 4
    const int bRowL = tid / 32;         // 0..7
    const int bColL = (tid % 32) * 4;   // 0..124

    float acc[TM][TN];
    #pragma unroll
    for (int i = 0; i < TM; i++)
        #pragma unroll
        for (int j = 0; j < TN; j++) acc[i][j] = 0.f;

    float regA[TM], regB[TN];

    for (int k0 = 0; k0 < K; k0 += BK) {
        float4 a4 = *(const float4*)(Ablk + (size_t)aRow * K + k0 + aCol);
        As[aCol + 0][aRow] = a4.x;
        As[aCol + 1][aRow] = a4.y;
        As[aCol + 2][aRow] = a4.z;
        As[aCol + 3][aRow] = a4.w;
        float4 b4 = *(const float4*)(Bblk + (size_t)(k0 + bRowL) * N + bColL);
        *(float4*)&Bs[bRowL][bColL] = b4;
        __syncthreads();

        #pragma unroll
        for (int kk = 0; kk < BK; kk++) {
            #pragma unroll
            for (int i = 0; i < TM; i++) regA[i] = As[kk][tRow * TM + i];
            #pragma unroll
            for (int j = 0; j < TN; j++) regB[j] = Bs[kk][tCol * TN + j];
            #pragma unroll
            for (int i = 0; i < TM; i++)
                #pragma unroll
                for (int j = 0; j < TN; j++)
                    acc[i][j] += regA[i] * regB[j];
        }
        __syncthreads();
    }

    #pragma unroll
    for (int i = 0; i < TM; i++) {
        int row = blockIdx.y * BM + tRow * TM + i;
        #pragma unroll
        for (int j = 0; j < TN; j += 4) {
            int col = blockIdx.x * BN + tCol * TN + j;
            float4 v;
            v.x = acc[i][j + 0] + bias[col + 0];
            v.y = acc[i][j + 1] + bias[col + 1];
            v.z = acc[i][j + 2] + bias[col + 2];
            v.w = acc[i][j + 3] + bias[col + 3];
            *(float4*)(C + (size_t)row * N + col) = v;
        }
    }
}

// ---------------------------------------------------------------------------
// Flash attention, fp32 SIMT. One thread per query row.
// grid: (SEQ/128, HEADS, BATCH), block: 128 threads.
// ---------------------------------------------------------------------------
__global__ __launch_bounds__(128)
void attn_kernel()
{
    const int KT = 64;                  // keys per smem tile
    const int b = blockIdx.z;
    const int h = blockIdx.y;
    const int q_row = blockIdx.x * 128 + threadIdx.x;

    __shared__ float Ks[KT][HD];
    __shared__ float Vs[KT][HD];

    // load this thread's query row (scaled by 1/sqrt(64))
    float q[HD];
    const float* qptr = g_qkv + ((size_t)(b * SEQ + q_row) * HEADS + h) * (3 * HD);
    #pragma unroll
    for (int d = 0; d < HD; d++) q[d] = qptr[d] * 0.125f;

    float o[HD];
    #pragma unroll
    for (int d = 0; d < HD; d++) o[d] = 0.f;
    float m = -1e30f, l = 0.f;

    for (int k0 = 0; k0 < SEQ; k0 += KT) {
        __syncthreads();
        // cooperative K/V tile load: KT*HD floats each, float4-vectorized
        for (int idx = threadIdx.x; idx < KT * HD / 4; idx += 128) {
            int e = idx * 4;
            int r = e / HD, c = e % HD;
            const float* kvp = g_qkv + ((size_t)(b * SEQ + k0 + r) * HEADS + h) * (3 * HD);
            *(float4*)&Ks[r][c] = *(const float4*)(kvp + HD + c);
            *(float4*)&Vs[r][c] = *(const float4*)(kvp + 2 * HD + c);
        }
        __syncthreads();

        #pragma unroll 1
        for (int j = 0; j < KT; j++) {
            float s = 0.f;
            #pragma unroll
            for (int d = 0; d < HD; d++) s += q[d] * Ks[j][d];
            if (s > m) {
                float corr = __expf(m - s);
                l *= corr;
                #pragma unroll
                for (int d = 0; d < HD; d++) o[d] *= corr;
                m = s;
            }
            float p = __expf(s - m);
            l += p;
            #pragma unroll
            for (int d = 0; d < HD; d++) o[d] += p * Vs[j][d];
        }
    }

    float inv = 1.f / l;
    float* optr = g_attn + ((size_t)(b * SEQ + q_row) * HEADS + h) * HD;
    #pragma unroll
    for (int d = 0; d < HD; d++) optr[d] = o[d] * inv;
}

// ---------------------------------------------------------------------------
extern "C" void kernel_launch(void* const* d_in, const int* in_sizes, int n_in,
                              void* d_out, int out_size)
{
    const float* X     = (const float*)d_in[0];   // [4,2048,1024]
    const float* W_qkv = (const float*)d_in[1];   // [1024,3072]
    const float* b_qkv = (const float*)d_in[2];   // [3072]
    const float* W_out = (const float*)d_in[3];   // [1024,1024]
    const float* b_out = (const float*)d_in[4];   // [1024]
    float* out = (float*)d_out;                   // [4,2048,1024]

    float* qkv;  cudaGetSymbolAddress((void**)&qkv,  g_qkv);
    float* attn; cudaGetSymbolAddress((void**)&attn, g_attn);

    // 1) QKV projection: [8192,1024] @ [1024,3072] + b_qkv
    {
        dim3 grid(QKV_COLS / 128, TOKENS / 128);
        sgemm_bias<<<grid, 256>>>(X, W_qkv, b_qkv, qkv, TOKENS, QKV_COLS, EMB);
    }

    // 2) Attention per (batch, head)
    {
        dim3 grid(SEQ / 128, HEADS, BATCH);
        attn_kernel<<<grid, 128>>>();
    }

    // 3) Output projection: [8192,1024] @ [1024,1024] + b_out
    {
        dim3 grid(EMB / 128, TOKENS / 128);
        sgemm_bias<<<grid, 256>>>(attn, W_out, b_out, out, TOKENS, EMB, EMB);
    }
}

// round 3
// speedup vs baseline: 1.4775x; 1.4775x over previous
#include <cuda_runtime.h>
#include <cuda_fp16.h>
#include <math.h>
#include <stdint.h>

#define BATCH 4
#define SEQ 2048
#define EMB 1024
#define HEADS 16
#define HD 64
#define TOKENS 8192
#define QKV_COLS 3072

// ---------------- scratch (static device globals) ----------------
__device__ float  g_qkv[TOKENS * QKV_COLS];        // fp32 QKV for attention
__device__ __half g_x16[TOKENS * EMB];             // X in fp16
__device__ __half g_wqkv_t[QKV_COLS * EMB];        // W_qkv^T  [N=3072][K=1024] fp16
__device__ __half g_wout_t[EMB * EMB];             // W_out^T  [N=1024][K=1024] fp16
__device__ __half g_attn16[TOKENS * EMB];          // attention output, fp16

__device__ __forceinline__ uint32_t smem_u32(const void* p) {
    uint32_t a;
    asm("{ .reg .u64 t; cvta.to.shared.u64 t, %1; cvt.u32.u64 %0, t; }" : "=r"(a) : "l"(p));
    return a;
}

// ---------------------------------------------------------------------------
// HMMA fp16 GEMM + bias:  C[M,N](f32) = A16[M,K] @ Bt16[N,K]^T + bias
// CTA tile 128x128, 8 warps (2x4), warp tile 64x32, K chunks of 64.
// grid=(N/128, M/128), 256 threads.
// ---------------------------------------------------------------------------
#define BK 64
#define APAD 8

__global__ __launch_bounds__(256)
void gemm_hmma(const __half* __restrict__ A, const __half* __restrict__ Bt,
               const float* __restrict__ bias, float* __restrict__ C,
               int M, int N, int K)
{
    __shared__ __half As[128][BK + APAD];
    __shared__ __half Bs[128][BK + APAD];

    const int tid = threadIdx.x;
    const int wid = tid >> 5, lane = tid & 31;
    const int warp_m = wid >> 2;          // 0..1
    const int warp_n = wid & 3;           // 0..3
    const int m0 = blockIdx.y * 128;
    const int n0 = blockIdx.x * 128;

    float acc[4][4][4];
    #pragma unroll
    for (int i = 0; i < 4; i++)
        #pragma unroll
        for (int j = 0; j < 4; j++)
            #pragma unroll
            for (int r = 0; r < 4; r++) acc[i][j][r] = 0.f;

    for (int k0 = 0; k0 < K; k0 += BK) {
        __syncthreads();
        // cooperative load: A tile [128 x 64], B tile [128 x 64], uint4 (8 halves)
        #pragma unroll
        for (int i = 0; i < 4; i++) {
            int idx = i * 256 + tid;           // 0..1023
            int row = idx >> 3, seg = idx & 7;
            *(uint4*)&As[row][seg * 8] = *(const uint4*)(A  + (size_t)(m0 + row) * K + k0 + seg * 8);
            *(uint4*)&Bs[row][seg * 8] = *(const uint4*)(Bt + (size_t)(n0 + row) * K + k0 + seg * 8);
        }
        __syncthreads();

        #pragma unroll
        for (int kk = 0; kk < BK; kk += 16) {
            uint32_t a[4][4], b[4][2];
            #pragma unroll
            for (int i = 0; i < 4; i++) {
                uint32_t addr = smem_u32(&As[warp_m * 64 + i * 16 + (lane & 15)][kk + (lane >> 4) * 8]);
                asm volatile("ldmatrix.sync.aligned.m8n8.x4.shared.b16 {%0,%1,%2,%3}, [%4];"
                             : "=r"(a[i][0]), "=r"(a[i][1]), "=r"(a[i][2]), "=r"(a[i][3]) : "r"(addr));
            }
            #pragma unroll
            for (int j = 0; j < 4; j++) {
                uint32_t addr = smem_u32(&Bs[warp_n * 32 + j * 8 + (lane & 7)][kk + ((lane >> 3) & 1) * 8]);
                asm volatile("ldmatrix.sync.aligned.m8n8.x2.shared.b16 {%0,%1}, [%2];"
                             : "=r"(b[j][0]), "=r"(b[j][1]) : "r"(addr));
            }
            #pragma unroll
            for (int i = 0; i < 4; i++)
                #pragma unroll
                for (int j = 0; j < 4; j++)
                    asm volatile("mma.sync.aligned.m16n8k16.row.col.f32.f16.f16.f32 "
                                 "{%0,%1,%2,%3}, {%4,%5,%6,%7}, {%8,%9}, {%0,%1,%2,%3};"
                                 : "+f"(acc[i][j][0]), "+f"(acc[i][j][1]),
                                   "+f"(acc[i][j][2]), "+f"(acc[i][j][3])
                                 : "r"(a[i][0]), "r"(a[i][1]), "r"(a[i][2]), "r"(a[i][3]),
                                   "r"(b[j][0]), "r"(b[j][1]));
        }
    }

    // epilogue: c0,c1 -> (row, col..col+1); c2,c3 -> (row+8, col..col+1)
    #pragma unroll
    for (int i = 0; i < 4; i++) {
        int r = m0 + warp_m * 64 + i * 16 + (lane >> 2);
        #pragma unroll
        for (int j = 0; j < 4; j++) {
            int c = n0 + warp_n * 32 + j * 8 + (lane & 3) * 2;
            float2 bv = *(const float2*)(bias + c);
            float2 v0 = make_float2(acc[i][j][0] + bv.x, acc[i][j][1] + bv.y);
            float2 v1 = make_float2(acc[i][j][2] + bv.x, acc[i][j][3] + bv.y);
            *(float2*)(C + (size_t)r * N + c) = v0;
            *(float2*)(C + (size_t)(r + 8) * N + c) = v1;
        }
    }
}

// ---------------------------------------------------------------------------
// conversion kernels
// ---------------------------------------------------------------------------
__global__ __launch_bounds__(256)
void conv_f32_f16(const float* __restrict__ in, __half* __restrict__ out)
{
    int i = (blockIdx.x * 256 + threadIdx.x) * 4;
    float4 v = *(const float4*)(in + i);
    __half2* o = (__half2*)(out + i);
    o[0] = __floats2half2_rn(v.x, v.y);
    o[1] = __floats2half2_rn(v.z, v.w);
}

// W [K][N] fp32 -> Wt [N][K] fp16 (tiled transpose)
__global__ __launch_bounds__(256)
void conv_transpose_f16(const float* __restrict__ W, __half* __restrict__ Wt, int K, int N)
{
    __shared__ float t[32][33];
    const int k0 = blockIdx.y * 32, n0 = blockIdx.x * 32;
    const int tx = threadIdx.x & 31, ty = threadIdx.x >> 5;  // 32 x 8
    #pragma unroll
    for (int r = ty; r < 32; r += 8)
        t[r][tx] = W[(size_t)(k0 + r) * N + n0 + tx];
    __syncthreads();
    #pragma unroll
    for (int r = ty; r < 32; r += 8)
        Wt[(size_t)(n0 + r) * K + k0 + tx] = __float2half(t[tx][r]);
}

// ---------------------------------------------------------------------------
// Flash attention, fp32 SIMT, float4 inner loops. Writes fp16 output.
// grid: (SEQ/128, HEADS, BATCH), 128 threads.
// ---------------------------------------------------------------------------
__global__ __launch_bounds__(128)
void attn_kernel()
{
    const int KT = 64;
    const int b = blockIdx.z, h = blockIdx.y;
    const int q_row = blockIdx.x * 128 + threadIdx.x;

    __shared__ float Ks[KT][HD];
    __shared__ float Vs[KT][HD];

    float4 q[16], o[16];
    const float* qptr = g_qkv + ((size_t)(b * SEQ + q_row) * HEADS + h) * (3 * HD);
    #pragma unroll
    for (int d = 0; d < 16; d++) {
        float4 v = *(const float4*)(qptr + d * 4);
        q[d].x = v.x * 0.125f; q[d].y = v.y * 0.125f;
        q[d].z = v.z * 0.125f; q[d].w = v.w * 0.125f;
        o[d] = make_float4(0.f, 0.f, 0.f, 0.f);
    }
    float m = -1e30f, l = 0.f;

    for (int k0 = 0; k0 < SEQ; k0 += KT) {
        __syncthreads();
        for (int idx = threadIdx.x; idx < KT * HD / 4; idx += 128) {
            int e = idx * 4;
            int r = e / HD, c = e % HD;
            const float* kvp = g_qkv + ((size_t)(b * SEQ + k0 + r) * HEADS + h) * (3 * HD);
            *(float4*)&Ks[r][c] = *(const float4*)(kvp + HD + c);
            *(float4*)&Vs[r][c] = *(const float4*)(kvp + 2 * HD + c);
        }
        __syncthreads();

        #pragma unroll 1
        for (int j = 0; j < KT; j++) {
            const float4* K4 = (const float4*)Ks[j];
            float s = 0.f;
            #pragma unroll
            for (int d = 0; d < 16; d++) {
                float4 kv = K4[d];
                s += q[d].x * kv.x + q[d].y * kv.y + q[d].z * kv.z + q[d].w * kv.w;
            }
            if (s > m) {
                float corr = __expf(m - s);
                l *= corr;
                #pragma unroll
                for (int d = 0; d < 16; d++) {
                    o[d].x *= corr; o[d].y *= corr; o[d].z *= corr; o[d].w *= corr;
                }
                m = s;
            }
            float p = __expf(s - m);
            l += p;
            const float4* V4 = (const float4*)Vs[j];
            #pragma unroll
            for (int d = 0; d < 16; d++) {
                float4 vv = V4[d];
                o[d].x += p * vv.x; o[d].y += p * vv.y;
                o[d].z += p * vv.z; o[d].w += p * vv.w;
            }
        }
    }

    float inv = 1.f / l;
    __half2* optr = (__half2*)(g_attn16 + ((size_t)(b * SEQ + q_row) * HEADS + h) * HD);
    #pragma unroll
    for (int d = 0; d < 16; d++) {
        optr[d * 2 + 0] = __floats2half2_rn(o[d].x * inv, o[d].y * inv);
        optr[d * 2 + 1] = __floats2half2_rn(o[d].z * inv, o[d].w * inv);
    }
}

// ---------------------------------------------------------------------------
extern "C" void kernel_launch(void* const* d_in, const int* in_sizes, int n_in,
                              void* d_out, int out_size)
{
    const float* X     = (const float*)d_in[0];
    const float* W_qkv = (const float*)d_in[1];
    const float* b_qkv = (const float*)d_in[2];
    const float* W_out = (const float*)d_in[3];
    const float* b_out = (const float*)d_in[4];
    float* out = (float*)d_out;

    float*  qkv;    cudaGetSymbolAddress((void**)&qkv,    g_qkv);
    __half* x16;    cudaGetSymbolAddress((void**)&x16,    g_x16);
    __half* wqkvt;  cudaGetSymbolAddress((void**)&wqkvt,  g_wqkv_t);
    __half* woutt;  cudaGetSymbolAddress((void**)&woutt,  g_wout_t);
    __half* attn16; cudaGetSymbolAddress((void**)&attn16, g_attn16);

    // conversions
    conv_f32_f16<<<(TOKENS * EMB) / 1024, 256>>>(X, x16);
    conv_transpose_f16<<<dim3(QKV_COLS / 32, EMB / 32), 256>>>(W_qkv, wqkvt, EMB, QKV_COLS);
    conv_transpose_f16<<<dim3(EMB / 32, EMB / 32), 256>>>(W_out, woutt, EMB, EMB);

    // 1) QKV projection (tensor cores, HMMA)
    gemm_hmma<<<dim3(QKV_COLS / 128, TOKENS / 128), 256>>>(
        x16, wqkvt, b_qkv, qkv, TOKENS, QKV_COLS, EMB);

    // 2) attention (fp32 SIMT, fp16 out)
    attn_kernel<<<dim3(SEQ / 128, HEADS, BATCH), 128>>>();

    // 3) output projection (tensor cores, HMMA)
    gemm_hmma<<<dim3(EMB / 128, TOKENS / 128), 256>>>(
        attn16, woutt, b_out, out, TOKENS, EMB, EMB);
}

// round 4
// speedup vs baseline: 8.0409x; 5.4423x over previous
#include <cuda_runtime.h>
#include <cuda_fp16.h>
#include <math.h>
#include <stdint.h>

#define BATCH 4
#define SEQ 2048
#define EMB 1024
#define HEADS 16
#define HD 64
#define TOKENS 8192
#define QKV_COLS 3072

// ---------------- scratch (static device globals) ----------------
__device__ __half g_qkv16[TOKENS * QKV_COLS];      // fp16 QKV: [token][h*192 + {q,k,v}*64]
__device__ __half g_x16[TOKENS * EMB];             // X in fp16
__device__ __half g_wqkv_t[QKV_COLS * EMB];        // W_qkv^T  [N=3072][K=1024] fp16
__device__ __half g_wout_t[EMB * EMB];             // W_out^T  [N=1024][K=1024] fp16
__device__ __half g_attn16[TOKENS * EMB];          // attention output, fp16

__device__ __forceinline__ uint32_t smem_u32(const void* p) {
    uint32_t a;
    asm("{ .reg .u64 t; cvta.to.shared.u64 t, %1; cvt.u32.u64 %0, t; }" : "=r"(a) : "l"(p));
    return a;
}
__device__ __forceinline__ float ex2(float x) {
    float y; asm("ex2.approx.f32 %0, %1;" : "=f"(y) : "f"(x)); return y;
}
#define MMA16816(d, a0, a1, a2, a3, b0, b1)                                     \
    asm volatile("mma.sync.aligned.m16n8k16.row.col.f32.f16.f16.f32 "           \
                 "{%0,%1,%2,%3}, {%4,%5,%6,%7}, {%8,%9}, {%0,%1,%2,%3};"        \
                 : "+f"((d)[0]), "+f"((d)[1]), "+f"((d)[2]), "+f"((d)[3])       \
                 : "r"(a0), "r"(a1), "r"(a2), "r"(a3), "r"(b0), "r"(b1))

// ---------------------------------------------------------------------------
// HMMA fp16 GEMM + bias:  C[M,N] = A16[M,K] @ Bt16[N,K]^T + bias
// CTA tile 128x128, 8 warps (2x4), warp tile 64x32, K chunks of 64.
// ---------------------------------------------------------------------------
#define BK 64
#define APAD 8

template<typename TOut>
__global__ __launch_bounds__(256)
void gemm_hmma(const __half* __restrict__ A, const __half* __restrict__ Bt,
               const float* __restrict__ bias, TOut* __restrict__ C,
               int M, int N, int K)
{
    __shared__ __half As[128][BK + APAD];
    __shared__ __half Bs[128][BK + APAD];

    const int tid = threadIdx.x;
    const int wid = tid >> 5, lane = tid & 31;
    const int warp_m = wid >> 2;
    const int warp_n = wid & 3;
    const int m0 = blockIdx.y * 128;
    const int n0 = blockIdx.x * 128;

    float acc[4][4][4];
    #pragma unroll
    for (int i = 0; i < 4; i++)
        #pragma unroll
        for (int j = 0; j < 4; j++)
            #pragma unroll
            for (int r = 0; r < 4; r++) acc[i][j][r] = 0.f;

    for (int k0 = 0; k0 < K; k0 += BK) {
        __syncthreads();
        #pragma unroll
        for (int i = 0; i < 4; i++) {
            int idx = i * 256 + tid;
            int row = idx >> 3, seg = idx & 7;
            *(uint4*)&As[row][seg * 8] = *(const uint4*)(A  + (size_t)(m0 + row) * K + k0 + seg * 8);
            *(uint4*)&Bs[row][seg * 8] = *(const uint4*)(Bt + (size_t)(n0 + row) * K + k0 + seg * 8);
        }
        __syncthreads();

        #pragma unroll
        for (int kk = 0; kk < BK; kk += 16) {
            uint32_t a[4][4], b[4][2];
            #pragma unroll
            for (int i = 0; i < 4; i++) {
                uint32_t addr = smem_u32(&As[warp_m * 64 + i * 16 + (lane & 15)][kk + (lane >> 4) * 8]);
                asm volatile("ldmatrix.sync.aligned.m8n8.x4.shared.b16 {%0,%1,%2,%3}, [%4];"
                             : "=r"(a[i][0]), "=r"(a[i][1]), "=r"(a[i][2]), "=r"(a[i][3]) : "r"(addr));
            }
            #pragma unroll
            for (int j = 0; j < 4; j++) {
                uint32_t addr = smem_u32(&Bs[warp_n * 32 + j * 8 + (lane & 7)][kk + ((lane >> 3) & 1) * 8]);
                asm volatile("ldmatrix.sync.aligned.m8n8.x2.shared.b16 {%0,%1}, [%2];"
                             : "=r"(b[j][0]), "=r"(b[j][1]) : "r"(addr));
            }
            #pragma unroll
            for (int i = 0; i < 4; i++)
                #pragma unroll
                for (int j = 0; j < 4; j++)
                    MMA16816(acc[i][j], a[i][0], a[i][1], a[i][2], a[i][3], b[j][0], b[j][1]);
        }
    }

    #pragma unroll
    for (int i = 0; i < 4; i++) {
        int r = m0 + warp_m * 64 + i * 16 + (lane >> 2);
        #pragma unroll
        for (int j = 0; j < 4; j++) {
            int c = n0 + warp_n * 32 + j * 8 + (lane & 3) * 2;
            float2 bv = *(const float2*)(bias + c);
            if constexpr (sizeof(TOut) == 2) {
                *(__half2*)((__half*)C + (size_t)r * N + c) =
                    __floats2half2_rn(acc[i][j][0] + bv.x, acc[i][j][1] + bv.y);
                *(__half2*)((__half*)C + (size_t)(r + 8) * N + c) =
                    __floats2half2_rn(acc[i][j][2] + bv.x, acc[i][j][3] + bv.y);
            } else {
                *(float2*)((float*)C + (size_t)r * N + c) =
                    make_float2(acc[i][j][0] + bv.x, acc[i][j][1] + bv.y);
                *(float2*)((float*)C + (size_t)(r + 8) * N + c) =
                    make_float2(acc[i][j][2] + bv.x, acc[i][j][3] + bv.y);
            }
        }
    }
}

// ---------------------------------------------------------------------------
// conversions
// ---------------------------------------------------------------------------
__global__ __launch_bounds__(256)
void conv_f32_f16(const float* __restrict__ in, __half* __restrict__ out)
{
    int i = (blockIdx.x * 256 + threadIdx.x) * 4;
    float4 v = *(const float4*)(in + i);
    __half2* o = (__half2*)(out + i);
    o[0] = __floats2half2_rn(v.x, v.y);
    o[1] = __floats2half2_rn(v.z, v.w);
}

__global__ __launch_bounds__(256)
void conv_transpose_f16(const float* __restrict__ W, __half* __restrict__ Wt, int K, int N)
{
    __shared__ float t[32][33];
    const int k0 = blockIdx.y * 32, n0 = blockIdx.x * 32;
    const int tx = threadIdx.x & 31, ty = threadIdx.x >> 5;
    #pragma unroll
    for (int r = ty; r < 32; r += 8)
        t[r][tx] = W[(size_t)(k0 + r) * N + n0 + tx];
    __syncthreads();
    #pragma unroll
    for (int r = ty; r < 32; r += 8)
        Wt[(size_t)(n0 + r) * K + k0 + tx] = __float2half(t[tx][r]);
}

// ---------------------------------------------------------------------------
// HMMA flash attention. grid (SEQ/128, HEADS, BATCH), 256 threads (8 warps).
// Warp w owns query rows 16w..16w+15 of the CTA's 128-row Q tile.
// ---------------------------------------------------------------------------
#define KPAD 8
#define KROW (HD + KPAD)   // 72

__global__ __launch_bounds__(256)
void attn_hmma()
{
    __shared__ __half sm[2][64][KROW];      // [0]=K tile, [1]=V tile; Q staged across both
    __half* Qs = &sm[0][0][0];              // [128][KROW] overlay

    const int tid = threadIdx.x, wid = tid >> 5, lane = tid & 31;
    const int b = blockIdx.z, h = blockIdx.y;
    const int q0 = blockIdx.x * 128;
    const __half* qkv = g_qkv16;
    const size_t base = (size_t)b * SEQ * QKV_COLS + (size_t)h * 192;

    // ---- stage Q tile [128 x 64] ----
    #pragma unroll
    for (int i = 0; i < 4; i++) {
        int idx = i * 256 + tid;            // 0..1023
        int row = idx >> 3, seg = idx & 7;
        *(uint4*)&Qs[row * KROW + seg * 8] =
            *(const uint4*)(qkv + base + (size_t)(q0 + row) * QKV_COLS + seg * 8);
    }
    __syncthreads();

    // ---- Q fragments (4 k-chunks) ----
    uint32_t qf[4][4];
    #pragma unroll
    for (int c = 0; c < 4; c++) {
        uint32_t addr = smem_u32(&Qs[(wid * 16 + (lane & 15)) * KROW + c * 16 + (lane >> 4) * 8]);
        asm volatile("ldmatrix.sync.aligned.m8n8.x4.shared.b16 {%0,%1,%2,%3}, [%4];"
                     : "=r"(qf[c][0]), "=r"(qf[c][1]), "=r"(qf[c][2]), "=r"(qf[c][3]) : "r"(addr));
    }

    float o[8][4];
    #pragma unroll
    for (int j = 0; j < 8; j++)
        #pragma unroll
        for (int r = 0; r < 4; r++) o[j][r] = 0.f;
    float m0 = -1e30f, m1 = -1e30f, l0 = 0.f, l1 = 0.f;
    const float SCALE = 0.125f * 1.4426950408889634f;   // softmax scale * log2(e)

    for (int t = 0; t < SEQ / 64; t++) {
        __syncthreads();
        // ---- load K,V tile (64 keys x 64 dims each) ----
        #pragma unroll
        for (int i = 0; i < 2; i++) {
            int idx = i * 256 + tid;        // 0..511
            int row = idx >> 3, seg = idx & 7;
            const __half* kp = qkv + base + (size_t)(t * 64 + row) * QKV_COLS + 64 + seg * 8;
            *(uint4*)&sm[0][row][seg * 8] = *(const uint4*)kp;          // K
            *(uint4*)&sm[1][row][seg * 8] = *(const uint4*)(kp + 64);   // V
        }
        __syncthreads();

        // ---- S = Q @ K^T  (8 n-blocks of 8 keys) ----
        float s[8][4];
        #pragma unroll
        for (int j = 0; j < 8; j++)
            #pragma unroll
            for (int r = 0; r < 4; r++) s[j][r] = 0.f;
        #pragma unroll
        for (int c = 0; c < 4; c++) {
            #pragma unroll
            for (int j = 0; j < 8; j++) {
                uint32_t b0, b1;
                uint32_t addr = smem_u32(&sm[0][j * 8 + (lane & 7)][c * 16 + ((lane >> 3) & 1) * 8]);
                asm volatile("ldmatrix.sync.aligned.m8n8.x2.shared.b16 {%0,%1}, [%2];"
                             : "=r"(b0), "=r"(b1) : "r"(addr));
                MMA16816(s[j], qf[c][0], qf[c][1], qf[c][2], qf[c][3], b0, b1);
            }
        }

        // ---- online softmax ----
        float mx0 = -1e30f, mx1 = -1e30f;
        #pragma unroll
        for (int j = 0; j < 8; j++) {
            s[j][0] *= SCALE; s[j][1] *= SCALE; s[j][2] *= SCALE; s[j][3] *= SCALE;
            mx0 = fmaxf(mx0, fmaxf(s[j][0], s[j][1]));
            mx1 = fmaxf(mx1, fmaxf(s[j][2], s[j][3]));
        }
        mx0 = fmaxf(mx0, __shfl_xor_sync(0xffffffff, mx0, 1));
        mx0 = fmaxf(mx0, __shfl_xor_sync(0xffffffff, mx0, 2));
        mx1 = fmaxf(mx1, __shfl_xor_sync(0xffffffff, mx1, 1));
        mx1 = fmaxf(mx1, __shfl_xor_sync(0xffffffff, mx1, 2));
        float m0n = fmaxf(m0, mx0), m1n = fmaxf(m1, mx1);
        float sc0 = ex2(m0 - m0n), sc1 = ex2(m1 - m1n);
        m0 = m0n; m1 = m1n;
        l0 *= sc0; l1 *= sc1;

        uint32_t pf[4][4];
        #pragma unroll
        for (int j = 0; j < 8; j++) {
            float p0 = ex2(s[j][0] - m0n), p1 = ex2(s[j][1] - m0n);
            float p2 = ex2(s[j][2] - m1n), p3 = ex2(s[j][3] - m1n);
            l0 += p0 + p1; l1 += p2 + p3;
            __half2 h01 = __floats2half2_rn(p0, p1);
            __half2 h23 = __floats2half2_rn(p2, p3);
            pf[j >> 1][(j & 1) * 2 + 0] = *(uint32_t*)&h01;
            pf[j >> 1][(j & 1) * 2 + 1] = *(uint32_t*)&h23;
        }

        #pragma unroll
        for (int j = 0; j < 8; j++) {
            o[j][0] *= sc0; o[j][1] *= sc0; o[j][2] *= sc1; o[j][3] *= sc1;
        }

        // ---- O += P @ V  (n-blocks over dim, k-chunks over keys) ----
        #pragma unroll
        for (int c = 0; c < 4; c++) {
            #pragma unroll
            for (int j = 0; j < 8; j++) {
                uint32_t b0, b1;
                uint32_t addr = smem_u32(&sm[1][c * 16 + (lane & 15)][j * 8]);
                asm volatile("ldmatrix.sync.aligned.m8n8.x2.trans.shared.b16 {%0,%1}, [%2];"
                             : "=r"(b0), "=r"(b1) : "r"(addr));
                MMA16816(o[j], pf[c][0], pf[c][1], pf[c][2], pf[c][3], b0, b1);
            }
        }
    }

    // ---- normalize + write fp16 output ----
    l0 += __shfl_xor_sync(0xffffffff, l0, 1);
    l0 += __shfl_xor_sync(0xffffffff, l0, 2);
    l1 += __shfl_xor_sync(0xffffffff, l1, 1);
    l1 += __shfl_xor_sync(0xffffffff, l1, 2);
    float i0 = 1.f / l0, i1 = 1.f / l1;

    const int r = q0 + wid * 16 + (lane >> 2);
    #pragma unroll
    for (int j = 0; j < 8; j++) {
        int col = h * HD + j * 8 + (lane & 3) * 2;
        *(__half2*)(g_attn16 + (size_t)(b * SEQ + r) * EMB + col) =
            __floats2half2_rn(o[j][0] * i0, o[j][1] * i0);
        *(__half2*)(g_attn16 + (size_t)(b * SEQ + r + 8) * EMB + col) =
            __floats2half2_rn(o[j][2] * i1, o[j][3] * i1);
    }
}

// ---------------------------------------------------------------------------
extern "C" void kernel_launch(void* const* d_in, const int* in_sizes, int n_in,
                              void* d_out, int out_size)
{
    const float* X     = (const float*)d_in[0];
    const float* W_qkv = (const float*)d_in[1];
    const float* b_qkv = (const float*)d_in[2];
    const float* W_out = (const float*)d_in[3];
    const float* b_out = (const float*)d_in[4];
    float* out = (float*)d_out;

    __half* qkv16;  cudaGetSymbolAddress((void**)&qkv16,  g_qkv16);
    __half* x16;    cudaGetSymbolAddress((void**)&x16,    g_x16);
    __half* wqkvt;  cudaGetSymbolAddress((void**)&wqkvt,  g_wqkv_t);
    __half* woutt;  cudaGetSymbolAddress((void**)&woutt,  g_wout_t);
    __half* attn16; cudaGetSymbolAddress((void**)&attn16, g_attn16);

    // conversions
    conv_f32_f16<<<(TOKENS * EMB) / 1024, 256>>>(X, x16);
    conv_transpose_f16<<<dim3(QKV_COLS / 32, EMB / 32), 256>>>(W_qkv, wqkvt, EMB, QKV_COLS);
    conv_transpose_f16<<<dim3(EMB / 32, EMB / 32), 256>>>(W_out, woutt, EMB, EMB);

    // 1) QKV projection -> fp16 QKV
    gemm_hmma<__half><<<dim3(QKV_COLS / 128, TOKENS / 128), 256>>>(
        x16, wqkvt, b_qkv, qkv16, TOKENS, QKV_COLS, EMB);

    // 2) flash attention (HMMA)
    attn_hmma<<<dim3(SEQ / 128, HEADS, BATCH), 256>>>();

    // 3) output projection -> fp32 out
    gemm_hmma<float><<<dim3(EMB / 128, TOKENS / 128), 256>>>(
        attn16, woutt, b_out, out, TOKENS, EMB, EMB);
}